// round 16
// baseline (speedup 1.0000x reference)
#include <cuda_runtime.h>

#define Bq 16
#define Sq 128
#define Dq 300
#define Oq 64
#define Eq 16
#define Tq 45
#define TP 48               // padded type count
#define ROWS_TOT 2048
#define WROW 316
#define KT 60               // K-chunk
#define CST 68              // smem col stride (floats): 272B = 17x16B, conflict-free LDS.128
#define NCOL 80             // 64 Wg | 16 C
#define BUFS (NCOL*CST)     // 5440 floats per buffer

// smem float offsets
#define OFF_SW   2400                       // after sh2 (4 pairs x 300 x 2)
#define OFF_SE   (OFF_SW + 2*BUFS)          // 13280: e[t] (64)
#define OFF_SDT  (OFF_SE + 64)              // 13344: dep_table (720)
#define OFF_SEXP (OFF_SDT + 720)            // 14064: E table (384)
#define SMEM_FLOATS (OFF_SEXP + 384)        // 14448 floats = 57792 B

// __device__ scratch (allocation-free rule; zero-initialized)
__device__ float g_ht[ROWS_TOT*Oq];
__device__ float g_C [Eq*304];      // C[e][k], rowlen 304 (cols 300..303 unused)
__device__ int   g_syncC;           // C-slice completion counter (target 60)
__device__ int   g_cntA[Bq];        // per-batch ht-done counters (target 16)
__device__ int   g_done;            // completion counter (target 256)

__device__ __forceinline__ void cp16(float* sdst, const float* gsrc) {
    unsigned a = (unsigned)__cvta_generic_to_shared(sdst);
    asm volatile("cp.async.cg.shared.global [%0], [%1], 16;" :: "r"(a), "l"(gsrc));
}

// ---------------------------------------------------------------------------
// Fused uniform kernel: 256 blocks x 256 threads, 57.8 KB smem, ONE WAVE
// (3 blocks/SM => 444 slots >= 256). Block bx owns rows bx*8 .. bx*8+7.
//   prologue: bx<60 produce C k-slice -> g_C (+g_syncC); all compute Q/cb/e[t].
//   mainloop: 80 cols (64 Wg + 16 C fused), f32x2 row-pair accumulation.
//   epilogue: ht -> g_ht (+cntA[b]); S-table+softmax -> smem E (no global).
//   attn:     spin cntA[b]==16, stage 32KB slab, gather+rowsum+matmul -> out.
// ---------------------------------------------------------------------------
__global__ void __launch_bounds__(256) fused_kernel(
        const float* __restrict__ h,
        const float* __restrict__ W1, const float* __restrict__ b1,
        const float* __restrict__ W2, const float* __restrict__ b2,
        const float* __restrict__ Wg, const float* __restrict__ bg,
        const float* __restrict__ dep_table,
        const unsigned char* __restrict__ mask8,
        const int* __restrict__ dep,
        const float* __restrict__ bias,
        float* __restrict__ out) {
    extern __shared__ float sm[];
    __shared__ int sp[5];
    __shared__ float swt[8];
    __shared__ float smx[8];
    __shared__ float sden[8];

    int tid = threadIdx.x;
    int bx  = blockIdx.x;
    int gr0 = bx * 8;
    int b   = gr0 >> 7;

    float* se  = sm + OFF_SE;
    float* sdt = sm + OFF_SDT;
    float* sE  = sm + OFF_SEXP;

    // ================= prologue: C slice + Q/cb/e[t] + sdt ==============
    {
        float* sWt1 = sm;            // tails [o][e] 1024
        float* sWt2 = sm + 1024;
        float* sW1c = sm + 2048;     // k-panel [o][j] 64*8 (pad 8)
        float* sW2c = sm + 2560;
        float* sb1  = sm + 3072;     // 64
        float* sb2  = sm + 3136;
        float* sQ   = sm + 3200;     // 256
        float* scb  = sm + 3456;     // 16

        int k0 = bx * 5;             // bx<60 covers k=0..299
        {
            int o = tid >> 2, q = tid & 3;
            *(float4*)&sWt1[o*Eq + q*4] = *(const float4*)&W1[o*WROW + Dq + q*4];
            *(float4*)&sWt2[o*Eq + q*4] = *(const float4*)&W2[o*WROW + Dq + q*4];
        }
        if (tid < 64) { sb1[tid] = b1[tid]; sb2[tid] = b2[tid]; }
        if (bx < 60 && tid < 64) {
            #pragma unroll
            for (int j = 0; j < 5; j++) {
                sW1c[tid*8 + j] = W1[tid*WROW + k0 + j];
                sW2c[tid*8 + j] = W2[tid*WROW + k0 + j];
            }
        }
        for (int i = tid; i < Tq*Eq; i += 256) sdt[i] = dep_table[i];
        __syncthreads();

        if (bx < 60 && tid < 80) {
            int e = tid & 15, j = tid >> 4;
            float acc = 0.f;
            #pragma unroll 8
            for (int o = 0; o < Oq; o++)
                acc += sW1c[o*8 + j] * sWt2[o*Eq + e]
                     + sW2c[o*8 + j] * sWt1[o*Eq + e];
            g_C[e*304 + k0 + j] = acc;
        }
        {
            int e = tid & 15, ep = tid >> 4;
            float q = 0.f;
            #pragma unroll 8
            for (int o = 0; o < Oq; o++)
                q += sWt1[o*Eq + e] * sWt2[o*Eq + ep];
            sQ[e*16 + ep] = q;
        }
        if (tid < 16) {
            float c = 0.f;
            #pragma unroll 8
            for (int o = 0; o < Oq; o++)
                c += sb1[o] * sWt2[o*Eq + tid] + sb2[o] * sWt1[o*Eq + tid];
            scb[tid] = c;
        }
        __threadfence();
        __syncthreads();
        if (bx < 60 && tid == 0) atomicAdd(&g_syncC, 1);

        if (tid < TP) {
            float ev = 0.f;
            if (tid < Tq) {
                float dte[Eq];
                #pragma unroll
                for (int e2 = 0; e2 < Eq; e2++) dte[e2] = sdt[tid*Eq + e2];
                #pragma unroll
                for (int e2 = 0; e2 < Eq; e2++) {
                    float row = scb[e2];
                    #pragma unroll
                    for (int e3 = 0; e3 < Eq; e3++)
                        row += sQ[e2*16 + e3] * dte[e3];
                    ev += dte[e2] * row;
                }
            }
            se[tid] = ev;
        }
    }

    // ================= span scan (dual bool-dtype robust) ================
    if (tid < 5) sp[tid] = (tid==0 || tid==3) ? Sq : ((tid==1 || tid==4) ? -1 : 0);
    __syncthreads();
    if (tid < 128 && mask8[(b<<7) + tid]) {
        atomicMin(&sp[0], tid); atomicMax(&sp[1], tid); atomicAdd(&sp[2], 1);
    }
    __syncthreads();
    bool valid8 = (sp[2] == 3 && sp[1] - sp[0] == 2);
    if (!valid8) {
        const int* m32 = (const int*)mask8;
        if (tid < 128 && m32[(b<<7) + tid] != 0) {
            atomicMin(&sp[3], tid); atomicMax(&sp[4], tid);
        }
    }
    __syncthreads();
    int st = valid8 ? sp[0] : sp[3];
    int en = valid8 ? sp[1] : sp[4];
    if (tid < 8) {
        int s = (gr0 + tid) & 127;
        float w;
        if (s < st)      w = 1.0f - (float)(st - s) * (1.0f/128.0f);
        else if (s > en) w = 1.0f - (float)(s - en) * (1.0f/128.0f);
        else             w = 0.0f;
        swt[tid] = w;
    }
    __syncthreads();

    // ---- stage position-weighted h (8 rows), packed row pairs ----
    float* sh2 = sm;
    {
        const float4* h4 = (const float4*)(h + (size_t)gr0 * Dq);
        for (int i = tid; i < 8*75; i += 256) {
            int r = i / 75, q = i - r*75;
            float4 v = h4[i];
            float w = swt[r];
            float* dst = sh2 + ((r >> 1)*300 + q*4)*2 + (r & 1);
            dst[0] = v.x*w; dst[2] = v.y*w; dst[4] = v.z*w; dst[6] = v.w*w;
        }
    }

    // wait for all C slices before staging C columns
    __syncthreads();
    if (tid == 0) {
        while (atomicAdd(&g_syncC, 0) < 60) __nanosleep(64);
        __threadfence();
    }
    __syncthreads();

    float* sW = sm + OFF_SW;
    #define STAGE_CHUNK(buf, cc)                                            \
        for (int i = tid; i < NCOL*15; i += 256) {                          \
            int col = i / 15, q = i - col*15;                               \
            const float* src = (col < 64)                                   \
                ? Wg  + (size_t)col * Dq  + (cc)*KT + q*4                   \
                : g_C + (size_t)(col-64) * 304 + (cc)*KT + q*4;             \
            cp16(&sW[(buf)*BUFS + col*CST + q*4], src);                     \
        }                                                                   \
        asm volatile("cp.async.commit_group;" ::: "memory");

    STAGE_CHUNK(0, 0)

    // mainloop mapping: accW = (col cg, pair pr); quad leaders also own
    // C output (e16 = q&15, pc = q>>4) with pc == pr (h pair reuse).
    int cg = tid & 63;
    int pr = tid >> 6;
    bool c4 = (tid & 3) == 0;
    int e16 = (tid >> 2) & 15;
    unsigned long long accW = 0ull, accC = 0ull;
    const unsigned long long* sh2u = (const unsigned long long*)sh2;

    for (int c = 0; c < 5; c++) {
        if (c < 4) { STAGE_CHUNK((c+1)&1, c+1) }
        if (c < 4) asm volatile("cp.async.wait_group 1;" ::: "memory");
        else       asm volatile("cp.async.wait_group 0;" ::: "memory");
        __syncthreads();

        const float* wp = sW + (c & 1)*BUFS + cg*CST;
        const float* cp = sW + (c & 1)*BUFS + (64 + e16)*CST;
        #pragma unroll 5
        for (int k4 = 0; k4 < 15; k4++) {
            float4 wv = *(const float4*)&wp[k4*4];
            const unsigned long long* hp = &sh2u[(size_t)pr*300 + c*KT + k4*4];
            ulonglong2 t0 = *(const ulonglong2*)(hp);
            ulonglong2 t1 = *(const ulonglong2*)(hp + 2);
            unsigned long long hk[4] = {t0.x, t0.y, t1.x, t1.y};
            #pragma unroll
            for (int kk = 0; kk < 4; kk++) {
                unsigned long long wpk;
                unsigned wu = __float_as_uint(((const float*)&wv)[kk]);
                asm("mov.b64 %0, {%1, %1};" : "=l"(wpk) : "r"(wu));
                asm("fma.rn.f32x2 %0, %1, %2, %0;"
                    : "+l"(accW) : "l"(hk[kk]), "l"(wpk));
            }
            if (c4) {
                float4 cv = *(const float4*)&cp[k4*4];
                #pragma unroll
                for (int kk = 0; kk < 4; kk++) {
                    unsigned long long cpk;
                    unsigned cu = __float_as_uint(((const float*)&cv)[kk]);
                    asm("mov.b64 %0, {%1, %1};" : "=l"(cpk) : "r"(cu));
                    asm("fma.rn.f32x2 %0, %1, %2, %0;"
                        : "+l"(accC) : "l"(hk[kk]), "l"(cpk));
                }
            }
        }
        __syncthreads();
    }

    // ================= epilogue =========================================
    // ht -> global, bump cntA[b]
    {
        float bt = bg[cg];
        unsigned lo = (unsigned)(accW & 0xffffffffu);
        unsigned hi = (unsigned)(accW >> 32);
        g_ht[(size_t)(gr0 + pr*2    )*Oq + cg] = __uint_as_float(lo) + bt;
        g_ht[(size_t)(gr0 + pr*2 + 1)*Oq + cg] = __uint_as_float(hi) + bt;
    }
    __syncthreads();
    if (tid == 0) { __threadfence(); atomicAdd(&g_cntA[b], 1); }

    // y -> smem (sW region dead), then S-table + softmax -> sE (local)
    float* sy = sm + OFF_SW;         // 8*16
    if (c4) {
        unsigned lo = (unsigned)(accC & 0xffffffffu);
        unsigned hi = (unsigned)(accC >> 32);
        sy[(pr*2    )*16 + e16] = __uint_as_float(lo);
        sy[(pr*2 + 1)*16 + e16] = __uint_as_float(hi);
    }
    __syncthreads();

    float* ssv = sm + OFF_SW + 128;  // 8*48
    for (int i = tid; i < 8*TP; i += 256) {
        int r = i / TP, t = i - r*TP;
        float s;
        if (t < Tq) {
            s = se[t];
            const float* yr = sy + r*16;
            const float* dt = sdt + t*16;
            #pragma unroll
            for (int e2 = 0; e2 < Eq; e2++) s += yr[e2]*dt[e2];
        } else s = -1e30f;
        ssv[i] = s;
    }
    __syncthreads();
    if (tid < 8) {
        float m = -1e30f;
        #pragma unroll 8
        for (int t = 0; t < TP; t++) m = fmaxf(m, ssv[tid*TP + t]);
        smx[tid] = m;
    }
    __syncthreads();
    for (int i = tid; i < 8*TP; i += 256) {
        int r = i / TP, t = i - r*TP;
        sE[i] = (t > 0 && t < Tq) ? __expf((ssv[i] - smx[r]) * 0.125f) : 0.f;
    }

    // wait for this batch's full g_ht slab
    __syncthreads();
    if (tid == 0) {
        while (atomicAdd(&g_cntA[b], 0) < 16) __nanosleep(128);
        __threadfence();
    }
    __syncthreads();

    // ================= attn =============================================
    float* sA  = sm;                 // 8*128 = 1024
    float* sht = sm + 1024;          // 128*64 = 8192 (below OFF_SE, safe)

    {
        const float* src = g_ht + ((size_t)b * Sq) * Oq;
        for (int i = tid; i < Sq*Oq/4; i += 256)
            cp16(&sht[i*4], src + i*4);
        asm volatile("cp.async.commit_group;" ::: "memory");
    }

    int g = tid >> 5, lane = tid & 31;    // warp g = row g
    {
        int4 d = *(const int4*)&dep[(size_t)(gr0 + g)*Sq + lane*4];
        const float* Eg = sE + g*TP;
        float e0 = Eg[d.x], e1 = Eg[d.y], e2 = Eg[d.z], e3 = Eg[d.w];
        *(float4*)&sA[g*Sq + lane*4] = make_float4(e0, e1, e2, e3);
        float s = e0 + e1 + e2 + e3;
        #pragma unroll
        for (int off = 16; off; off >>= 1)
            s += __shfl_xor_sync(0xffffffffu, s, off);
        if (lane == 0) sden[g] = 1.0f / (s + 1e-6f);
    }
    asm volatile("cp.async.wait_group 0;" ::: "memory");
    __syncthreads();

    const float* Ar = sA + g*Sq;
    float a0 = 0.f, a1 = 0.f;
    #pragma unroll 8
    for (int u4 = 0; u4 < 32; u4++) {
        float4 av = *(const float4*)&Ar[u4*4];
        const float* hb = sht + (u4*4)*Oq + lane;
        a0 += av.x*hb[0*Oq]      + av.y*hb[1*Oq]      + av.z*hb[2*Oq]      + av.w*hb[3*Oq];
        a1 += av.x*hb[0*Oq + 32] + av.y*hb[1*Oq + 32] + av.z*hb[2*Oq + 32] + av.w*hb[3*Oq + 32];
    }
    float den = sden[g];
    out[(size_t)(gr0 + g)*Oq + lane]      = fmaxf(a0*den + bias[lane], 0.f);
    out[(size_t)(gr0 + g)*Oq + lane + 32] = fmaxf(a1*den + bias[lane + 32], 0.f);

    // completion; 256th block resets flags for next graph replay
    if (tid == 0) {
        int vdone = atomicAdd(&g_done, 1);
        if (vdone == 255) {
            g_done = 0;
            g_syncC = 0;
            #pragma unroll
            for (int i = 0; i < Bq; i++) g_cntA[i] = 0;
        }
    }
    #undef STAGE_CHUNK
}

// ---------------------------------------------------------------------------
// Inputs: h, dep_table, W1, b1, W2, b2, Wg, bg, bias, dep_type_matrix, aspect_mask
// ---------------------------------------------------------------------------
extern "C" void kernel_launch(void* const* d_in, const int* in_sizes, int n_in,
                              void* d_out, int out_size) {
    const float* h         = (const float*)d_in[0];
    const float* dep_table = (const float*)d_in[1];
    const float* W1        = (const float*)d_in[2];
    const float* b1        = (const float*)d_in[3];
    const float* W2        = (const float*)d_in[4];
    const float* b2        = (const float*)d_in[5];
    const float* Wg        = (const float*)d_in[6];
    const float* bg        = (const float*)d_in[7];
    const float* bias      = (const float*)d_in[8];
    const int*   dep       = (const int*)d_in[9];
    const unsigned char* mask = (const unsigned char*)d_in[10];

    const int smem = SMEM_FLOATS * (int)sizeof(float);   // 57792 B
    cudaFuncSetAttribute(fused_kernel,
                         cudaFuncAttributeMaxDynamicSharedMemorySize, smem);

    fused_kernel<<<256, 256, smem>>>(h, W1, b1, W2, b2, Wg, bg,
                                     dep_table, mask, dep, bias, (float*)d_out);
}

// round 17
// speedup vs baseline: 1.0067x; 1.0067x over previous
#include <cuda_runtime.h>

#define Bq 16
#define Sq 128
#define Dq 300
#define Oq 64
#define Eq 16
#define Tq 45
#define TP 48               // padded type count
#define ROWS_TOT 2048
#define WROW 316
#define KT 60               // K-chunk
#define CST 68              // smem col stride (floats): 272B, conflict-free LDS.128
#define NCOL 80             // 64 Wg | 16 C
#define BUFS (NCOL*CST)     // 5440 floats per buffer

// smem float offsets
#define OFF_SW   2400                       // after sh2 (4 pairs x 300 x 2)
#define OFF_SE   (OFF_SW + 2*BUFS)          // 13280: e[t] (64)
#define OFF_SDT  (OFF_SE + 64)              // 13344: dep_table (720)
#define OFF_SEXP (OFF_SDT + 720)            // 14064: E table (384)
#define SMEM_FLOATS (OFF_SEXP + 384)        // 14448 floats = 57792 B

// __device__ scratch (allocation-free rule; zero-initialized)
__device__ float g_ht[ROWS_TOT*Oq];
__device__ float g_C [Eq*304];      // C[e][k], rowlen 304
__device__ int   g_syncC;           // C-slice completion counter (target 60)
__device__ int   g_cntA[Bq];        // per-batch ht-done counters (target 16)
__device__ int   g_done;            // completion counter (target 256)

__device__ __forceinline__ void cp16(float* sdst, const float* gsrc) {
    unsigned a = (unsigned)__cvta_generic_to_shared(sdst);
    asm volatile("cp.async.cg.shared.global [%0], [%1], 16;" :: "r"(a), "l"(gsrc));
}
#define NBAR(id) asm volatile("bar.sync %0, 256;" :: "r"(id) : "memory")

// ---------------------------------------------------------------------------
// Fused uniform kernel: 256 blocks x 512 threads, 57.8 KB smem, ONE WAVE.
// Two 256-thread split-K groups (kh=0: chunks 0-2, kh=1: chunks 3-4), each
// single-buffered, synced by named barriers; f32x2 partials reduced in smem.
// ---------------------------------------------------------------------------
__global__ void __launch_bounds__(512) fused_kernel(
        const float* __restrict__ h,
        const float* __restrict__ W1, const float* __restrict__ b1,
        const float* __restrict__ W2, const float* __restrict__ b2,
        const float* __restrict__ Wg, const float* __restrict__ bg,
        const float* __restrict__ dep_table,
        const unsigned char* __restrict__ mask8,
        const int* __restrict__ dep,
        const float* __restrict__ bias,
        float* __restrict__ out) {
    extern __shared__ float sm[];
    __shared__ int sp[5];
    __shared__ float swt[8];
    __shared__ float smx[8];
    __shared__ float sden[8];

    int tid = threadIdx.x;
    int bx  = blockIdx.x;
    int gr0 = bx * 8;
    int b   = gr0 >> 7;

    float* se  = sm + OFF_SE;
    float* sdt = sm + OFF_SDT;
    float* sE  = sm + OFF_SEXP;

    // ================= prologue: C slice + Q/cb/e[t] + sdt ==============
    {
        float* sWt1 = sm;            // tails [o][e] 1024
        float* sWt2 = sm + 1024;
        float* sW1c = sm + 2048;     // k-panel [o][j] 64*8
        float* sW2c = sm + 2560;
        float* sb1  = sm + 3072;     // 64
        float* sb2  = sm + 3136;
        float* sQ   = sm + 3200;     // 256
        float* scb  = sm + 3456;     // 16

        int k0 = bx * 5;             // bx<60 covers k=0..299
        if (tid < 256) {
            int o = tid >> 2, q = tid & 3;
            *(float4*)&sWt1[o*Eq + q*4] = *(const float4*)&W1[o*WROW + Dq + q*4];
            *(float4*)&sWt2[o*Eq + q*4] = *(const float4*)&W2[o*WROW + Dq + q*4];
        }
        if (tid < 64) { sb1[tid] = b1[tid]; sb2[tid] = b2[tid]; }
        if (bx < 60 && tid >= 256 && tid < 320) {
            int o = tid - 256;
            #pragma unroll
            for (int j = 0; j < 5; j++) {
                sW1c[o*8 + j] = W1[o*WROW + k0 + j];
                sW2c[o*8 + j] = W2[o*WROW + k0 + j];
            }
        }
        for (int i = tid; i < Tq*Eq; i += 512) sdt[i] = dep_table[i];
        __syncthreads();

        if (bx < 60 && tid >= 256 && tid < 336) {
            int t2 = tid - 256;
            int e = t2 & 15, j = t2 >> 4;
            float acc = 0.f;
            #pragma unroll 8
            for (int o = 0; o < Oq; o++)
                acc += sW1c[o*8 + j] * sWt2[o*Eq + e]
                     + sW2c[o*8 + j] * sWt1[o*Eq + e];
            g_C[e*304 + k0 + j] = acc;
        }
        if (tid < 256) {
            int e = tid & 15, ep = tid >> 4;
            float q = 0.f;
            #pragma unroll 8
            for (int o = 0; o < Oq; o++)
                q += sWt1[o*Eq + e] * sWt2[o*Eq + ep];
            sQ[e*16 + ep] = q;
        }
        if (tid >= 336 && tid < 352) {
            int e = tid - 336;
            float c = 0.f;
            #pragma unroll 8
            for (int o = 0; o < Oq; o++)
                c += sb1[o] * sWt2[o*Eq + e] + sb2[o] * sWt1[o*Eq + e];
            scb[e] = c;
        }
        __threadfence();
        __syncthreads();
        if (bx < 60 && tid == 0) atomicAdd(&g_syncC, 1);

        if (tid < TP) {
            float ev = 0.f;
            if (tid < Tq) {
                float dte[Eq];
                #pragma unroll
                for (int e2 = 0; e2 < Eq; e2++) dte[e2] = sdt[tid*Eq + e2];
                #pragma unroll
                for (int e2 = 0; e2 < Eq; e2++) {
                    float row = scb[e2];
                    #pragma unroll
                    for (int e3 = 0; e3 < Eq; e3++)
                        row += sQ[e2*16 + e3] * dte[e3];
                    ev += dte[e2] * row;
                }
            }
            se[tid] = ev;
        }
    }

    // ================= span scan (dual bool-dtype robust) ================
    if (tid < 5) sp[tid] = (tid==0 || tid==3) ? Sq : ((tid==1 || tid==4) ? -1 : 0);
    __syncthreads();
    if (tid < 128 && mask8[(b<<7) + tid]) {
        atomicMin(&sp[0], tid); atomicMax(&sp[1], tid); atomicAdd(&sp[2], 1);
    }
    __syncthreads();
    bool valid8 = (sp[2] == 3 && sp[1] - sp[0] == 2);
    if (!valid8) {
        const int* m32 = (const int*)mask8;
        if (tid < 128 && m32[(b<<7) + tid] != 0) {
            atomicMin(&sp[3], tid); atomicMax(&sp[4], tid);
        }
    }
    __syncthreads();
    int st = valid8 ? sp[0] : sp[3];
    int en = valid8 ? sp[1] : sp[4];
    if (tid < 8) {
        int s = (gr0 + tid) & 127;
        float w;
        if (s < st)      w = 1.0f - (float)(st - s) * (1.0f/128.0f);
        else if (s > en) w = 1.0f - (float)(s - en) * (1.0f/128.0f);
        else             w = 0.0f;
        swt[tid] = w;
    }
    __syncthreads();

    // ---- stage position-weighted h (8 rows), packed row pairs ----
    float* sh2 = sm;
    {
        const float4* h4 = (const float4*)(h + (size_t)gr0 * Dq);
        for (int i = tid; i < 8*75; i += 512) {
            int r = i / 75, q = i - r*75;
            float4 v = h4[i];
            float w = swt[r];
            float* dst = sh2 + ((r >> 1)*300 + q*4)*2 + (r & 1);
            dst[0] = v.x*w; dst[2] = v.y*w; dst[4] = v.z*w; dst[6] = v.w*w;
        }
    }

    // wait for all C slices before staging C columns
    __syncthreads();
    if (tid == 0) {
        while (atomicAdd(&g_syncC, 0) < 60) __nanosleep(64);
        __threadfence();
    }
    __syncthreads();

    // ================= split-K mainloop ==================================
    int kh   = tid >> 8;          // group 0: chunks 0..2, group 1: chunks 3..4
    int ltid = tid & 255;
    int cg = ltid & 63;
    int pr = ltid >> 6;
    bool c4 = (ltid & 3) == 0;
    int e16 = (ltid >> 2) & 15;

    float* sW = sm + OFF_SW;
    float* myBuf = sW + kh*BUFS;
    unsigned long long accW = 0ull, accC = 0ull;
    const unsigned long long* sh2u = (const unsigned long long*)sh2;

    int cbeg = kh ? 3 : 0, cend = kh ? 5 : 3;
    for (int c = cbeg; c < cend; c++) {
        for (int i = ltid; i < NCOL*15; i += 256) {
            int col = i / 15, q = i - col*15;
            const float* src = (col < 64)
                ? Wg  + (size_t)col * Dq  + c*KT + q*4
                : g_C + (size_t)(col-64) * 304 + c*KT + q*4;
            cp16(&myBuf[col*CST + q*4], src);
        }
        asm volatile("cp.async.commit_group;" ::: "memory");
        asm volatile("cp.async.wait_group 0;" ::: "memory");
        NBAR(1 + kh);

        const float* wp = myBuf + cg*CST;
        const float* cpp = myBuf + (64 + e16)*CST;
        #pragma unroll 5
        for (int k4 = 0; k4 < 15; k4++) {
            float4 wv = *(const float4*)&wp[k4*4];
            const unsigned long long* hp = &sh2u[(size_t)pr*300 + c*KT + k4*4];
            ulonglong2 t0 = *(const ulonglong2*)(hp);
            ulonglong2 t1 = *(const ulonglong2*)(hp + 2);
            unsigned long long hk[4] = {t0.x, t0.y, t1.x, t1.y};
            #pragma unroll
            for (int kk = 0; kk < 4; kk++) {
                unsigned long long wpk;
                unsigned wu = __float_as_uint(((const float*)&wv)[kk]);
                asm("mov.b64 %0, {%1, %1};" : "=l"(wpk) : "r"(wu));
                asm("fma.rn.f32x2 %0, %1, %2, %0;"
                    : "+l"(accW) : "l"(hk[kk]), "l"(wpk));
            }
            if (c4) {
                float4 cv = *(const float4*)&cpp[k4*4];
                #pragma unroll
                for (int kk = 0; kk < 4; kk++) {
                    unsigned long long cpk;
                    unsigned cu = __float_as_uint(((const float*)&cv)[kk]);
                    asm("mov.b64 %0, {%1, %1};" : "=l"(cpk) : "r"(cu));
                    asm("fma.rn.f32x2 %0, %1, %2, %0;"
                        : "+l"(accC) : "l"(hk[kk]), "l"(cpk));
                }
            }
        }
        NBAR(1 + kh);
    }

    // ---- cross-group reduction (f32x2 adds) ----
    __syncthreads();
    unsigned long long* redW = (unsigned long long*)(sm + OFF_SW);       // 256 u64
    unsigned long long* redC = (unsigned long long*)(sm + OFF_SW + 512); // 64 u64
    if (kh == 1) {
        redW[ltid] = accW;
        if (c4) redC[ltid >> 2] = accC;
    }
    __syncthreads();
    if (kh == 0) {
        unsigned long long o1 = redW[ltid];
        asm("add.rn.f32x2 %0, %0, %1;" : "+l"(accW) : "l"(o1));
        if (c4) {
            unsigned long long o2 = redC[ltid >> 2];
            asm("add.rn.f32x2 %0, %0, %1;" : "+l"(accC) : "l"(o2));
        }
    }

    // ================= epilogue =========================================
    float* sy = sm + OFF_SW + 1024;       // 8*16
    if (kh == 0) {
        float bt = bg[cg];
        unsigned lo = (unsigned)(accW & 0xffffffffu);
        unsigned hi = (unsigned)(accW >> 32);
        g_ht[(size_t)(gr0 + pr*2    )*Oq + cg] = __uint_as_float(lo) + bt;
        g_ht[(size_t)(gr0 + pr*2 + 1)*Oq + cg] = __uint_as_float(hi) + bt;
        if (c4) {
            unsigned clo = (unsigned)(accC & 0xffffffffu);
            unsigned chi = (unsigned)(accC >> 32);
            sy[(pr*2    )*16 + e16] = __uint_as_float(clo);
            sy[(pr*2 + 1)*16 + e16] = __uint_as_float(chi);
        }
    }
    __syncthreads();
    if (tid == 0) { __threadfence(); atomicAdd(&g_cntA[b], 1); }

    // S-table + softmax -> sE (local)
    float* ssv = sm + OFF_SW + 1024 + 128;  // 8*48
    for (int i = tid; i < 8*TP; i += 512) {
        int r = i / TP, t = i - r*TP;
        float s;
        if (t < Tq) {
            s = se[t];
            const float* yr = sy + r*16;
            const float* dt = sdt + t*16;
            #pragma unroll
            for (int e2 = 0; e2 < Eq; e2++) s += yr[e2]*dt[e2];
        } else s = -1e30f;
        ssv[i] = s;
    }
    __syncthreads();
    if (tid < 8) {
        float m = -1e30f;
        #pragma unroll 8
        for (int t = 0; t < TP; t++) m = fmaxf(m, ssv[tid*TP + t]);
        smx[tid] = m;
    }
    __syncthreads();
    for (int i = tid; i < 8*TP; i += 512) {
        int r = i / TP, t = i - r*TP;
        sE[i] = (t > 0 && t < Tq) ? __expf((ssv[i] - smx[r]) * 0.125f) : 0.f;
    }
    __syncthreads();

    // ================= attn =============================================
    float* sA  = sm;                 // 8*128 = 1024
    float* sht = sm + 1024;          // 128*64 = 8192

    int w = tid >> 5, lane = tid & 31;
    int row = w >> 1, oh = w & 1;

    // gather + row-sum BEFORE the cross-block wait (needs only dep + sE)
    if (oh == 0) {
        int4 d = *(const int4*)&dep[(size_t)(gr0 + row)*Sq + lane*4];
        const float* Eg = sE + row*TP;
        float e0 = Eg[d.x], e1 = Eg[d.y], e2 = Eg[d.z], e3 = Eg[d.w];
        *(float4*)&sA[row*Sq + lane*4] = make_float4(e0, e1, e2, e3);
        float s = e0 + e1 + e2 + e3;
        #pragma unroll
        for (int off = 16; off; off >>= 1)
            s += __shfl_xor_sync(0xffffffffu, s, off);
        if (lane == 0) sden[row] = 1.0f / (s + 1e-6f);
    }

    // wait for this batch's full g_ht slab
    if (tid == 0) {
        while (atomicAdd(&g_cntA[b], 0) < 16) __nanosleep(128);
        __threadfence();
    }
    __syncthreads();

    {
        const float* src = g_ht + ((size_t)b * Sq) * Oq;
        for (int i = tid; i < Sq*Oq/4; i += 512)
            cp16(&sht[i*4], src + i*4);
        asm volatile("cp.async.commit_group;" ::: "memory");
        asm volatile("cp.async.wait_group 0;" ::: "memory");
    }
    __syncthreads();

    // matmul: 2 warps per row, each covers one o-half (32 outputs)
    {
        int o = oh*32 + lane;
        const float* Ar = sA + row*Sq;
        float a = 0.f;
        #pragma unroll 8
        for (int u4 = 0; u4 < 32; u4++) {
            float4 av = *(const float4*)&Ar[u4*4];
            const float* hb = sht + (u4*4)*Oq + o;
            a += av.x*hb[0*Oq] + av.y*hb[1*Oq] + av.z*hb[2*Oq] + av.w*hb[3*Oq];
        }
        out[(size_t)(gr0 + row)*Oq + o] = fmaxf(a*sden[row] + bias[o], 0.f);
    }

    // completion; 256th block resets flags for next graph replay
    if (tid == 0) {
        int vdone = atomicAdd(&g_done, 1);
        if (vdone == 255) {
            g_done = 0;
            g_syncC = 0;
            #pragma unroll
            for (int i = 0; i < Bq; i++) g_cntA[i] = 0;
        }
    }
}

// ---------------------------------------------------------------------------
// Inputs: h, dep_table, W1, b1, W2, b2, Wg, bg, bias, dep_type_matrix, aspect_mask
// ---------------------------------------------------------------------------
extern "C" void kernel_launch(void* const* d_in, const int* in_sizes, int n_in,
                              void* d_out, int out_size) {
    const float* h         = (const float*)d_in[0];
    const float* dep_table = (const float*)d_in[1];
    const float* W1        = (const float*)d_in[2];
    const float* b1        = (const float*)d_in[3];
    const float* W2        = (const float*)d_in[4];
    const float* b2        = (const float*)d_in[5];
    const float* Wg        = (const float*)d_in[6];
    const float* bg        = (const float*)d_in[7];
    const float* bias      = (const float*)d_in[8];
    const int*   dep       = (const int*)d_in[9];
    const unsigned char* mask = (const unsigned char*)d_in[10];

    const int smem = SMEM_FLOATS * (int)sizeof(float);   // 57792 B
    cudaFuncSetAttribute(fused_kernel,
                         cudaFuncAttributeMaxDynamicSharedMemorySize, smem);

    fused_kernel<<<256, 512, smem>>>(h, W1, b1, W2, b2, Wg, bg,
                                     dep_table, mask, dep, bias, (float*)d_out);
}